// round 7
// baseline (speedup 1.0000x reference)
#include <cuda_runtime.h>

#define H 1024
#define W 2048
#define B 8
#define N 64
#define WM    (W - 1)     // 2047, power-of-two mod mask
#define FULL  0xffffffffu

#define WARPS_PER_BLK 8
#define GRID_X (N / WARPS_PER_BLK)    // 8
#define NBLK   (GRID_X * B)           // 64

// Packed finalize scratch: bits [52..] = block count, bits [0..52) = biased
// fixed-point partial sum (scale 2^24, bias 2^40 per block; 64*2^40 << 2^52,
// no carry into count). One atomicAdd per block; same-address RMW total order
// means the count==64 observer sees the complete sum -- no fences.
__device__ unsigned long long g_pack = 0ull;

#define FP_SCALE 16777216.0f            // 2^24
#define FP_BIAS  (1ll << 40)

__global__ void __launch_bounds__(32 * WARPS_PER_BLK)
spherical_nss_kernel(const float* __restrict__ y_pred,
                     const float* __restrict__ fixations,
                     const float* __restrict__ edge_vals,
                     const int*   __restrict__ ker_ws,
                     float* __restrict__ d_out) {
    const int b    = blockIdx.y;
    const int l    = threadIdx.x & 31;
    const int warp = threadIdx.x >> 5;
    const int i    = blockIdx.x * WARPS_PER_BLK + warp;  // fixation index 0..63

    __shared__ float swarp[WARPS_PER_BLK];

    // Each lane rounds 2 fixations of batch b (rintf == jnp.rint). All warps
    // in the block read the same 512B -> L1 broadcast after first warp.
    const float2* fx = (const float2*)fixations + b * N;
    float2 f0 = __ldg(&fx[l]);
    float2 f1 = __ldg(&fx[l + 32]);
    int x0 = (int)rintf(f0.x * (float)(W - 1));
    int y0 = (int)rintf(f0.y * (float)(H - 1));
    int x1 = (int)rintf(f1.x * (float)(W - 1));
    int y1 = (int)rintf(f1.y * (float)(H - 1));

    // This warp's task row via shuffle.
    int yi = (i < 32) ? __shfl_sync(FULL, y0, i) : __shfl_sync(FULL, y1, i - 32);

    // 64-bit mask of fixations in this batch hitting row yi.
    unsigned lo = __ballot_sync(FULL, y0 == yi);
    unsigned hi = __ballot_sync(FULL, y1 == yi);
    unsigned long long mask =
        ((unsigned long long)hi << 32) | (unsigned long long)lo;

    float acc = 0.0f;
    // Dedup: only the first fixation index hitting this row processes it.
    if (!(i > 0 && (mask & ((1ull << i) - 1ull)))) {
        const float* row = y_pred + ((size_t)b * H + yi) * W;

        if (yi == 0 || yi == H - 1) {
            // Pole: whole row forced to 1.0 -> fully unrolled vector sum.
            const float4* row4 = (const float4*)row;
            #pragma unroll
            for (int k = 0; k < W / 4 / 32; ++k) {
                float4 v = __ldg(&row4[l + 32 * k]);
                acc += (v.x + v.y) + (v.z + v.w);
            }
        } else {
            const int   kw  = __ldg(&ker_ws[yi]);
            const float ev  = __ldg(&edge_vals[yi]);
            const int   cnt = __popcll(mask);

            if (cnt <= 4) {
                // Matched lefts in ascending fixation order (scan order).
                int mlefts[4];
                unsigned long long mm = mask;
                #pragma unroll
                for (int j = 0; j < 4; ++j) {
                    int n = __ffsll(mm) - 1;   // garbage when j >= cnt (unused)
                    mm &= mm - 1;
                    int xn = (n < 32) ? __shfl_sync(FULL, x0, n)
                                      : __shfl_sync(FULL, x1, n & 31);
                    mlefts[j] = xn - (kw >> 1);
                }
                // Column's final value comes from the LAST covering fixation;
                // assign each covered column to that fixation only.
                #pragma unroll
                for (int j = 0; j < 4; ++j) {
                    if (j >= cnt) break;
                    const int left = mlefts[j];
                    for (int off = l; off < kw; off += 32) {
                        int c = (left + off) & WM;
                        bool covered_later = false;
                        #pragma unroll
                        for (int j2 = j + 1; j2 < 4; ++j2) {
                            if (j2 < cnt) {
                                int o2 = (c - mlefts[j2]) & WM;
                                covered_later |= (o2 < kw);
                            }
                        }
                        if (!covered_later) {
                            float v = (off == 0 || off == kw - 1) ? ev : 1.0f;
                            acc += v * __ldg(&row[c]);
                        }
                    }
                }
            } else {
                // Vanishingly rare: full-width replay in scan order.
                for (int c = l; c < W; c += 32) {
                    float v = 0.0f;
                    unsigned long long m = mask;
                    while (m) {
                        int n = __ffsll(m) - 1;
                        m &= m - 1;
                        int xn = (n < 32) ? __shfl_sync(FULL, x0, n)
                                          : __shfl_sync(FULL, x1, n & 31);
                        int off = (c - (xn - (kw >> 1))) & WM;
                        if (off < kw)
                            v = (off == 0 || off == kw - 1) ? ev : 1.0f;
                    }
                    acc += v * __ldg(&row[c]);
                }
            }
        }
    }

    // Warp reduce.
    #pragma unroll
    for (int s = 16; s > 0; s >>= 1)
        acc += __shfl_down_sync(FULL, acc, s);
    if (l == 0) swarp[warp] = acc;
    __syncthreads();

    if (threadIdx.x == 0) {
        // Deterministic in-order sum of the 8 warp partials.
        float block_acc = swarp[0];
        #pragma unroll
        for (int wgi = 1; wgi < WARPS_PER_BLK; ++wgi) block_acc += swarp[wgi];

        // Single packed atomic per block.
        long long fixedv = __float2ll_rn(block_acc * FP_SCALE) + FP_BIAS;
        unsigned long long pack = (1ull << 52) | (unsigned long long)fixedv;
        unsigned long long old = atomicAdd(&g_pack, pack);
        if ((old >> 52) == NBLK - 1) {
            unsigned long long tot = old + pack;
            long long sum_fixed =
                (long long)(tot & ((1ull << 52) - 1ull)) -
                (long long)NBLK * FP_BIAS;
            float total = (float)sum_fixed * (1.0f / FP_SCALE);
            d_out[0] = total * (1.0f / ((float)N * (float)B));
            atomicExch(&g_pack, 0ull);   // reset for next graph replay
        }
    }
}

extern "C" void kernel_launch(void* const* d_in, const int* in_sizes, int n_in,
                              void* d_out, int out_size) {
    const float* y_pred    = (const float*)d_in[0];
    const float* fixations = (const float*)d_in[1];
    const float* edge_vals = (const float*)d_in[2];
    const int*   ker_ws    = (const int*)d_in[3];

    dim3 grid(GRID_X, B);
    spherical_nss_kernel<<<grid, 32 * WARPS_PER_BLK>>>(
        y_pred, fixations, edge_vals, ker_ws, (float*)d_out);
}

// round 8
// speedup vs baseline: 1.2593x; 1.2593x over previous
#include <cuda_runtime.h>

#define H 1024
#define W 2048
#define B 8
#define N 64
#define NTASK (B * N)     // 512
#define WM    (W - 1)     // 2047, power-of-two mod mask
#define FULL  0xffffffffu

#define WARPS_PER_BLK 4
#define GRID_X (N / WARPS_PER_BLK)    // 16

// Packed finalize scratch: bits [52..] = warp count, bits [0..52) = biased
// fixed-point partial sum (scale 2^24, bias 2^40 per warp; 512*2^40 < 2^49,
// no carry into count). One atomicAdd per warp; same-address RMW total order
// means the count==512 observer sees the complete sum -- no fences needed.
__device__ unsigned long long g_pack = 0ull;

#define FP_SCALE 16777216.0f            // 2^24
#define FP_BIAS  (1ll << 40)

__global__ void __launch_bounds__(32 * WARPS_PER_BLK)
spherical_nss_kernel(const float* __restrict__ y_pred,
                     const float* __restrict__ fixations,
                     const float* __restrict__ edge_vals,
                     const int*   __restrict__ ker_ws,
                     float* __restrict__ d_out) {
    const int b    = blockIdx.y;
    const int l    = threadIdx.x & 31;
    const int warp = threadIdx.x >> 5;
    const int i    = blockIdx.x * WARPS_PER_BLK + warp;  // fixation idx 0..63

    // Each lane rounds 2 fixations of batch b (rintf == jnp.rint). Warps in
    // a CTA share these 512B via L1; warps stay fully independent otherwise.
    const float2* fx = (const float2*)fixations + b * N;
    float2 f0 = __ldg(&fx[l]);
    float2 f1 = __ldg(&fx[l + 32]);
    int x0 = (int)rintf(f0.x * (float)(W - 1));
    int y0 = (int)rintf(f0.y * (float)(H - 1));
    int x1 = (int)rintf(f1.x * (float)(W - 1));
    int y1 = (int)rintf(f1.y * (float)(H - 1));

    // This warp's task row via shuffle.
    int yi = (i < 32) ? __shfl_sync(FULL, y0, i) : __shfl_sync(FULL, y1, i - 32);

    // 64-bit mask of fixations in this batch hitting row yi.
    unsigned lo = __ballot_sync(FULL, y0 == yi);
    unsigned hi = __ballot_sync(FULL, y1 == yi);
    unsigned long long mask =
        ((unsigned long long)hi << 32) | (unsigned long long)lo;

    float acc = 0.0f;
    // Dedup: only the first fixation index hitting this row processes it.
    if (!(i > 0 && (mask & ((1ull << i) - 1ull)))) {
        const float* row = y_pred + ((size_t)b * H + yi) * W;

        if (yi == 0 || yi == H - 1) {
            // Pole: whole row forced to 1.0 -> fully unrolled vector sum.
            const float4* row4 = (const float4*)row;
            #pragma unroll
            for (int k = 0; k < W / 4 / 32; ++k) {
                float4 v = __ldg(&row4[l + 32 * k]);
                acc += (v.x + v.y) + (v.z + v.w);
            }
        } else {
            const int   kw  = __ldg(&ker_ws[yi]);
            const float ev  = __ldg(&edge_vals[yi]);
            const int   cnt = __popcll(mask);

            if (cnt <= 4) {
                // Matched lefts in ascending fixation order (scan order).
                int mlefts[4];
                unsigned long long mm = mask;
                #pragma unroll
                for (int j = 0; j < 4; ++j) {
                    int n = __ffsll(mm) - 1;   // garbage when j >= cnt (unused)
                    mm &= mm - 1;
                    int xn = (n < 32) ? __shfl_sync(FULL, x0, n)
                                      : __shfl_sync(FULL, x1, n & 31);
                    mlefts[j] = xn - (kw >> 1);
                }
                // Column's final value comes from the LAST covering fixation;
                // assign each covered column to that fixation only.
                #pragma unroll
                for (int j = 0; j < 4; ++j) {
                    if (j >= cnt) break;
                    const int left = mlefts[j];
                    for (int off = l; off < kw; off += 32) {
                        int c = (left + off) & WM;
                        bool covered_later = false;
                        #pragma unroll
                        for (int j2 = j + 1; j2 < 4; ++j2) {
                            if (j2 < cnt) {
                                int o2 = (c - mlefts[j2]) & WM;
                                covered_later |= (o2 < kw);
                            }
                        }
                        if (!covered_later) {
                            float v = (off == 0 || off == kw - 1) ? ev : 1.0f;
                            acc += v * __ldg(&row[c]);
                        }
                    }
                }
            } else {
                // Vanishingly rare: full-width replay in scan order.
                for (int c = l; c < W; c += 32) {
                    float v = 0.0f;
                    unsigned long long m = mask;
                    while (m) {
                        int n = __ffsll(m) - 1;
                        m &= m - 1;
                        int xn = (n < 32) ? __shfl_sync(FULL, x0, n)
                                          : __shfl_sync(FULL, x1, n & 31);
                        int off = (c - (xn - (kw >> 1))) & WM;
                        if (off < kw)
                            v = (off == 0 || off == kw - 1) ? ev : 1.0f;
                    }
                    acc += v * __ldg(&row[c]);
                }
            }
        }
    }

    // Warp reduce; one packed atomic per warp (no cross-warp coupling).
    #pragma unroll
    for (int s = 16; s > 0; s >>= 1)
        acc += __shfl_down_sync(FULL, acc, s);

    if (l == 0) {
        long long fixedv = __float2ll_rn(acc * FP_SCALE) + FP_BIAS;
        unsigned long long pack = (1ull << 52) | (unsigned long long)fixedv;
        unsigned long long old = atomicAdd(&g_pack, pack);
        if ((old >> 52) == NTASK - 1) {
            unsigned long long tot = old + pack;
            long long sum_fixed =
                (long long)(tot & ((1ull << 52) - 1ull)) -
                (long long)NTASK * FP_BIAS;
            float total = (float)sum_fixed * (1.0f / FP_SCALE);
            d_out[0] = total * (1.0f / ((float)N * (float)B));
            atomicExch(&g_pack, 0ull);   // reset for next graph replay
        }
    }
}

extern "C" void kernel_launch(void* const* d_in, const int* in_sizes, int n_in,
                              void* d_out, int out_size) {
    const float* y_pred    = (const float*)d_in[0];
    const float* fixations = (const float*)d_in[1];
    const float* edge_vals = (const float*)d_in[2];
    const int*   ker_ws    = (const int*)d_in[3];

    dim3 grid(GRID_X, B);
    spherical_nss_kernel<<<grid, 32 * WARPS_PER_BLK>>>(
        y_pred, fixations, edge_vals, ker_ws, (float*)d_out);
}

// round 10
// speedup vs baseline: 1.3077x; 1.0385x over previous
#include <cuda_runtime.h>

#define H 1024
#define W 2048
#define B 8
#define N 64
#define NTASK (B * N)     // 512
#define WM    (W - 1)     // 2047, power-of-two mod mask
#define FULL  0xffffffffu

#define WARPS_PER_BLK 4
#define GRID_X (N / WARPS_PER_BLK)    // 16

// Speculative window: 7 iters x 32 lanes = 224 columns centered on xi.
// Max non-pole kw for H=1024 is kw(y=1) ~= 219 < 224, so the window always
// covers a single fixation's kernel. HALF_WIN = 112.
#define SPEC_ITERS 7
#define HALF_WIN   112

// Packed finalize scratch: bits [52..] = warp count, bits [0..52) = biased
// fixed-point partial sum (scale 2^24, bias 2^40 per warp; 512*2^40 < 2^49,
// no carry into count). One atomicAdd per warp; same-address RMW total order
// means the count==512 observer sees the complete sum -- no fences needed.
__device__ unsigned long long g_pack = 0ull;

#define FP_SCALE 16777216.0f            // 2^24
#define FP_BIAS  (1ll << 40)

__global__ void __launch_bounds__(32 * WARPS_PER_BLK)
spherical_nss_kernel(const float* __restrict__ y_pred,
                     const float* __restrict__ fixations,
                     const float* __restrict__ edge_vals,
                     const int*   __restrict__ ker_ws,
                     float* __restrict__ d_out) {
    const int b    = blockIdx.y;
    const int l    = threadIdx.x & 31;
    const int warp = threadIdx.x >> 5;
    const int i    = blockIdx.x * WARPS_PER_BLK + warp;  // fixation idx 0..63

    // RT1: fixations of batch b (rintf == jnp.rint). Warps in a CTA share
    // these 512B via L1; warps stay fully independent otherwise.
    const float2* fx = (const float2*)fixations + b * N;
    float2 f0 = __ldg(&fx[l]);
    float2 f1 = __ldg(&fx[l + 32]);
    int x0 = (int)rintf(f0.x * (float)(W - 1));
    int y0 = (int)rintf(f0.y * (float)(H - 1));
    int x1 = (int)rintf(f1.x * (float)(W - 1));
    int y1 = (int)rintf(f1.y * (float)(H - 1));

    // This warp's task (x, y) via shuffle.
    int yi = (i < 32) ? __shfl_sync(FULL, y0, i) : __shfl_sync(FULL, y1, i - 32);
    int xi = (i < 32) ? __shfl_sync(FULL, x0, i) : __shfl_sync(FULL, x1, i - 32);

    // 64-bit mask of fixations in this batch hitting row yi.
    unsigned lo = __ballot_sync(FULL, y0 == yi);
    unsigned hi = __ballot_sync(FULL, y1 == yi);
    unsigned long long mask =
        ((unsigned long long)hi << 32) | (unsigned long long)lo;

    float acc = 0.0f;
    // Dedup: only the first fixation index hitting this row processes it.
    if (!(i > 0 && (mask & ((1ull << i) - 1ull)))) {
        const float* row = y_pred + ((size_t)b * H + yi) * W;

        if (yi == 0 || yi == H - 1) {
            // Pole: whole row forced to 1.0 -> fully unrolled vector sum (RT2).
            const float4* row4 = (const float4*)row;
            #pragma unroll
            for (int k = 0; k < W / 4 / 32; ++k) {
                float4 v = __ldg(&row4[l + 32 * k]);
                acc += (v.x + v.y) + (v.z + v.w);
            }
        } else {
            const int cnt = __popcll(mask);

            if (cnt == 1) {
                // RT2 (all concurrent): kw, ev, and a speculative 224-col
                // window around xi that is guaranteed to cover the kernel.
                float spec[SPEC_ITERS];
                #pragma unroll
                for (int k = 0; k < SPEC_ITERS; ++k)
                    spec[k] = __ldg(&row[(xi - HALF_WIN + l + 32 * k) & WM]);
                const int   kw = __ldg(&ker_ws[yi]);
                const float ev = __ldg(&edge_vals[yi]);

                // Select from registers: spec pos p = l + 32k holds column
                // (xi - HALF_WIN + p); its kernel offset is p - HALF_WIN + kw/2.
                const int half = kw >> 1;
                #pragma unroll
                for (int k = 0; k < SPEC_ITERS; ++k) {
                    int off = l + 32 * k - HALF_WIN + half;
                    if (off >= 0 && off < kw) {
                        float v = (off == 0 || off == kw - 1) ? ev : 1.0f;
                        acc += v * spec[k];
                    }
                }
            } else {
                const int   kw = __ldg(&ker_ws[yi]);
                const float ev = __ldg(&edge_vals[yi]);

                if (cnt <= 4) {
                    // Matched lefts in ascending fixation order (scan order).
                    int mlefts[4];
                    unsigned long long mm = mask;
                    #pragma unroll
                    for (int j = 0; j < 4; ++j) {
                        int n = __ffsll(mm) - 1;  // garbage when j >= cnt
                        mm &= mm - 1;
                        int xn = (n < 32) ? __shfl_sync(FULL, x0, n)
                                          : __shfl_sync(FULL, x1, n & 31);
                        mlefts[j] = xn - (kw >> 1);
                    }
                    // Column's final value comes from the LAST covering
                    // fixation; assign each covered column to it only.
                    #pragma unroll
                    for (int j = 0; j < 4; ++j) {
                        if (j >= cnt) break;
                        const int left = mlefts[j];
                        for (int off = l; off < kw; off += 32) {
                            int c = (left + off) & WM;
                            bool covered_later = false;
                            #pragma unroll
                            for (int j2 = j + 1; j2 < 4; ++j2) {
                                if (j2 < cnt) {
                                    int o2 = (c - mlefts[j2]) & WM;
                                    covered_later |= (o2 < kw);
                                }
                            }
                            if (!covered_later) {
                                float v = (off == 0 || off == kw - 1) ? ev : 1.0f;
                                acc += v * __ldg(&row[c]);
                            }
                        }
                    }
                } else {
                    // Vanishingly rare: full-width replay in scan order.
                    for (int c = l; c < W; c += 32) {
                        float v = 0.0f;
                        unsigned long long m = mask;
                        while (m) {
                            int n = __ffsll(m) - 1;
                            m &= m - 1;
                            int xn = (n < 32) ? __shfl_sync(FULL, x0, n)
                                              : __shfl_sync(FULL, x1, n & 31);
                            int off = (c - (xn - (kw >> 1))) & WM;
                            if (off < kw)
                                v = (off == 0 || off == kw - 1) ? ev : 1.0f;
                        }
                        acc += v * __ldg(&row[c]);
                    }
                }
            }
        }
    }

    // Warp reduce; one packed atomic per warp (no cross-warp coupling).
    #pragma unroll
    for (int s = 16; s > 0; s >>= 1)
        acc += __shfl_down_sync(FULL, acc, s);

    if (l == 0) {
        long long fixedv = __float2ll_rn(acc * FP_SCALE) + FP_BIAS;
        unsigned long long pack = (1ull << 52) | (unsigned long long)fixedv;
        unsigned long long old = atomicAdd(&g_pack, pack);
        if ((old >> 52) == NTASK - 1) {
            unsigned long long tot = old + pack;
            long long sum_fixed =
                (long long)(tot & ((1ull << 52) - 1ull)) -
                (long long)NTASK * FP_BIAS;
            float total = (float)sum_fixed * (1.0f / FP_SCALE);
            d_out[0] = total * (1.0f / ((float)N * (float)B));
            atomicExch(&g_pack, 0ull);   // reset for next graph replay
        }
    }
}

extern "C" void kernel_launch(void* const* d_in, const int* in_sizes, int n_in,
                              void* d_out, int out_size) {
    const float* y_pred    = (const float*)d_in[0];
    const float* fixations = (const float*)d_in[1];
    const float* edge_vals = (const float*)d_in[2];
    const int*   ker_ws    = (const int*)d_in[3];

    dim3 grid(GRID_X, B);
    spherical_nss_kernel<<<grid, 32 * WARPS_PER_BLK>>>(
        y_pred, fixations, edge_vals, ker_ws, (float*)d_out);
}

// round 11
// speedup vs baseline: 1.3204x; 1.0097x over previous
#include <cuda_runtime.h>

#define H 1024
#define W 2048
#define B 8
#define N 64
#define NTASK (B * N)     // 512
#define WM    (W - 1)     // 2047, power-of-two mod mask
#define FULL  0xffffffffu

#define WARPS_PER_BLK 4
#define GRID_X (N / WARPS_PER_BLK)    // 16

// Speculative window: 7 iters x 32 lanes = 224 columns centered on xi.
// Max non-pole kw for H=1024 is kw(y=1) ~= 219 < 224, so the window always
// covers a single fixation's kernel. HALF_WIN = 112.
#define SPEC_ITERS 7
#define HALF_WIN   112

// Two-level packed finalize (all fixed-point -> replay-deterministic).
// Level 1: one counter per batch on its own 128B line. Warp pack:
//   bits [52..] count (64 max), bits [0..52) biased sum (scale 2^24,
//   bias 2^40/warp; 64*(2^40+eps) < 2^47 ✓, 64<<52 = 2^58 ✓).
// Level 2: batch observers add (batch_sum + 2^50) with count at bit 57
//   (8*2^51 < 2^54 ✓). Final observer writes d_out; observers reset their
//   own counters for the next graph replay. Same-address RMW total order
//   makes each observer see a complete sum -- no fences anywhere.
__device__ unsigned long long g_batch[B * 16];   // stride 16 ull = 128B
__device__ unsigned long long g_final = 0ull;

#define FP_SCALE 16777216.0f            // 2^24
#define FP_BIAS  (1ll << 40)
#define FP_BIAS2 (1ll << 50)
#define L1_CNT   (1ull << 52)
#define L1_MASK  ((1ull << 52) - 1ull)
#define L2_CNT   (1ull << 57)
#define L2_MASK  ((1ull << 57) - 1ull)

__global__ void __launch_bounds__(32 * WARPS_PER_BLK)
spherical_nss_kernel(const float* __restrict__ y_pred,
                     const float* __restrict__ fixations,
                     const float* __restrict__ edge_vals,
                     const int*   __restrict__ ker_ws,
                     float* __restrict__ d_out) {
    const int b    = blockIdx.y;
    const int l    = threadIdx.x & 31;
    const int warp = threadIdx.x >> 5;
    const int i    = blockIdx.x * WARPS_PER_BLK + warp;  // fixation idx 0..63

    // RT1: fixations of batch b (rintf == jnp.rint). Warps in a CTA share
    // these 512B via L1; warps stay fully independent otherwise.
    const float2* fx = (const float2*)fixations + b * N;
    float2 f0 = __ldg(&fx[l]);
    float2 f1 = __ldg(&fx[l + 32]);
    int x0 = (int)rintf(f0.x * (float)(W - 1));
    int y0 = (int)rintf(f0.y * (float)(H - 1));
    int x1 = (int)rintf(f1.x * (float)(W - 1));
    int y1 = (int)rintf(f1.y * (float)(H - 1));

    // This warp's task (x, y) via shuffle.
    int yi = (i < 32) ? __shfl_sync(FULL, y0, i) : __shfl_sync(FULL, y1, i - 32);
    int xi = (i < 32) ? __shfl_sync(FULL, x0, i) : __shfl_sync(FULL, x1, i - 32);

    // 64-bit mask of fixations in this batch hitting row yi.
    unsigned lo = __ballot_sync(FULL, y0 == yi);
    unsigned hi = __ballot_sync(FULL, y1 == yi);
    unsigned long long mask =
        ((unsigned long long)hi << 32) | (unsigned long long)lo;

    float acc = 0.0f;
    // Dedup: only the first fixation index hitting this row processes it.
    if (!(i > 0 && (mask & ((1ull << i) - 1ull)))) {
        const float* row = y_pred + ((size_t)b * H + yi) * W;

        if (yi == 0 || yi == H - 1) {
            // Pole: whole row forced to 1.0 -> fully unrolled vector sum (RT2).
            const float4* row4 = (const float4*)row;
            #pragma unroll
            for (int k = 0; k < W / 4 / 32; ++k) {
                float4 v = __ldg(&row4[l + 32 * k]);
                acc += (v.x + v.y) + (v.z + v.w);
            }
        } else {
            const int cnt = __popcll(mask);

            if (cnt == 1) {
                // RT2 (all concurrent): kw, ev, and a speculative 224-col
                // window around xi that is guaranteed to cover the kernel.
                float spec[SPEC_ITERS];
                #pragma unroll
                for (int k = 0; k < SPEC_ITERS; ++k)
                    spec[k] = __ldg(&row[(xi - HALF_WIN + l + 32 * k) & WM]);
                const int   kw = __ldg(&ker_ws[yi]);
                const float ev = __ldg(&edge_vals[yi]);

                // Select from registers: spec pos p = l + 32k holds column
                // (xi - HALF_WIN + p); kernel offset = p - HALF_WIN + kw/2.
                const int half = kw >> 1;
                #pragma unroll
                for (int k = 0; k < SPEC_ITERS; ++k) {
                    int off = l + 32 * k - HALF_WIN + half;
                    if (off >= 0 && off < kw) {
                        float v = (off == 0 || off == kw - 1) ? ev : 1.0f;
                        acc += v * spec[k];
                    }
                }
            } else {
                const int   kw = __ldg(&ker_ws[yi]);
                const float ev = __ldg(&edge_vals[yi]);

                if (cnt <= 4) {
                    // Matched lefts in ascending fixation order (scan order).
                    int mlefts[4];
                    unsigned long long mm = mask;
                    #pragma unroll
                    for (int j = 0; j < 4; ++j) {
                        int n = __ffsll(mm) - 1;  // garbage when j >= cnt
                        mm &= mm - 1;
                        int xn = (n < 32) ? __shfl_sync(FULL, x0, n)
                                          : __shfl_sync(FULL, x1, n & 31);
                        mlefts[j] = xn - (kw >> 1);
                    }
                    // Column's final value comes from the LAST covering
                    // fixation; assign each covered column to it only.
                    #pragma unroll
                    for (int j = 0; j < 4; ++j) {
                        if (j >= cnt) break;
                        const int left = mlefts[j];
                        for (int off = l; off < kw; off += 32) {
                            int c = (left + off) & WM;
                            bool covered_later = false;
                            #pragma unroll
                            for (int j2 = j + 1; j2 < 4; ++j2) {
                                if (j2 < cnt) {
                                    int o2 = (c - mlefts[j2]) & WM;
                                    covered_later |= (o2 < kw);
                                }
                            }
                            if (!covered_later) {
                                float v = (off == 0 || off == kw - 1) ? ev : 1.0f;
                                acc += v * __ldg(&row[c]);
                            }
                        }
                    }
                } else {
                    // Vanishingly rare: full-width replay in scan order.
                    for (int c = l; c < W; c += 32) {
                        float v = 0.0f;
                        unsigned long long m = mask;
                        while (m) {
                            int n = __ffsll(m) - 1;
                            m &= m - 1;
                            int xn = (n < 32) ? __shfl_sync(FULL, x0, n)
                                              : __shfl_sync(FULL, x1, n & 31);
                            int off = (c - (xn - (kw >> 1))) & WM;
                            if (off < kw)
                                v = (off == 0 || off == kw - 1) ? ev : 1.0f;
                        }
                        acc += v * __ldg(&row[c]);
                    }
                }
            }
        }
    }

    // Warp reduce.
    #pragma unroll
    for (int s = 16; s > 0; s >>= 1)
        acc += __shfl_down_sync(FULL, acc, s);

    if (l == 0) {
        // Level 1: per-batch packed atomic (8 parallel 64-deep chains).
        long long fixedv = __float2ll_rn(acc * FP_SCALE) + FP_BIAS;
        unsigned long long pack = L1_CNT | (unsigned long long)fixedv;
        unsigned long long old = atomicAdd(&g_batch[b * 16], pack);
        if ((old >> 52) == N - 1) {
            // Batch observer: complete batch sum; feed level 2; reset own.
            unsigned long long tot = old + pack;
            long long bsum = (long long)(tot & L1_MASK) - (long long)N * FP_BIAS;
            atomicExch(&g_batch[b * 16], 0ull);

            unsigned long long pack2 =
                L2_CNT | (unsigned long long)(bsum + FP_BIAS2);
            unsigned long long old2 = atomicAdd(&g_final, pack2);
            if ((old2 >> 57) == B - 1) {
                unsigned long long tot2 = old2 + pack2;
                long long sum_fixed =
                    (long long)(tot2 & L2_MASK) - (long long)B * FP_BIAS2;
                float total = (float)sum_fixed * (1.0f / FP_SCALE);
                d_out[0] = total * (1.0f / ((float)N * (float)B));
                atomicExch(&g_final, 0ull);   // reset for next replay
            }
        }
    }
}

extern "C" void kernel_launch(void* const* d_in, const int* in_sizes, int n_in,
                              void* d_out, int out_size) {
    const float* y_pred    = (const float*)d_in[0];
    const float* fixations = (const float*)d_in[1];
    const float* edge_vals = (const float*)d_in[2];
    const int*   ker_ws    = (const int*)d_in[3];

    dim3 grid(GRID_X, B);
    spherical_nss_kernel<<<grid, 32 * WARPS_PER_BLK>>>(
        y_pred, fixations, edge_vals, ker_ws, (float*)d_out);
}